// round 2
// baseline (speedup 1.0000x reference)
#include <cuda_runtime.h>

#define TT 1024
#define BB 512
#define DD 128
#define NO 11              // k-index: 0=f,1=i,2=o,3..10=g0..g7
#define PSTR (NO*BB)

__device__ float g_pre[TT * NO * BB];   // ~23 MB scratch, [t][k][B]

// ---------------------------------------------------------------------------
// Phase 1: pre[t,k,b] = dot(Wrow_k[0:128], x[t,b,:]) + bias_k
// ---------------------------------------------------------------------------
__device__ __forceinline__ float f4c(const float4 v, int kk){
    return kk==0 ? v.x : kk==1 ? v.y : kk==2 ? v.z : v.w;
}

__global__ void __launch_bounds__(128) prep_kernel(
    const float* __restrict__ x,
    const float* __restrict__ Wf, const float* __restrict__ bf,
    const float* __restrict__ Wi, const float* __restrict__ bi,
    const float* __restrict__ Wu, const float* __restrict__ bu,
    const float* __restrict__ Wo, const float* __restrict__ bo)
{
    __shared__ __align__(16) float wsm[DD*12];
    __shared__ float bsm[12];
    const int tid = threadIdx.x;
    {
        const int k = tid;                 // 128 threads <-> 128 k values
        wsm[k*12+0] = Wf[k];               // row 0 of Wf
        wsm[k*12+1] = Wi[k];
        wsm[k*12+2] = Wo[k];
#pragma unroll
        for (int u = 0; u < 8; u++) wsm[k*12+3+u] = Wu[u*136 + k];
        wsm[k*12+11] = 0.0f;
        if (tid == 0){
            bsm[0] = bf[0]; bsm[1] = bi[0]; bsm[2] = bo[0];
            for (int u = 0; u < 8; u++) bsm[3+u] = bu[u];
            bsm[11] = 0.0f;
        }
    }
    __syncthreads();

    const long long n0 = ((long long)blockIdx.x*128 + tid) * 4; // first of 4 tokens
    const float4* __restrict__ xp = (const float4*)x + n0*(DD/4);

    float acc[4][NO];
#pragma unroll
    for (int r = 0; r < 4; r++)
#pragma unroll
        for (int j = 0; j < NO; j++) acc[r][j] = bsm[j];

#pragma unroll 2
    for (int c = 0; c < 32; c++){
        float4 xv[4];
#pragma unroll
        for (int r = 0; r < 4; r++) xv[r] = xp[r*32 + c];
#pragma unroll
        for (int kk = 0; kk < 4; kk++){
            const int k = c*4 + kk;
            const float4* wr = (const float4*)&wsm[k*12];
            const float4 wa = wr[0], wb = wr[1], wc = wr[2];
            const float w[NO] = {wa.x,wa.y,wa.z,wa.w, wb.x,wb.y,wb.z,wb.w,
                                 wc.x,wc.y,wc.z};
#pragma unroll
            for (int r = 0; r < 4; r++){
                const float xs = f4c(xv[r], kk);
#pragma unroll
                for (int j = 0; j < NO; j++)
                    acc[r][j] = fmaf(xs, w[j], acc[r][j]);
            }
        }
    }

    const int t = (int)(n0 >> 9);          // n0 / 512
    const int b = (int)(n0 & 511);         // multiple of 4 -> float4 aligned
    float* op = g_pre + (long long)t*PSTR + b;
#pragma unroll
    for (int j = 0; j < NO; j++)
        *(float4*)(op + j*BB) = make_float4(acc[0][j],acc[1][j],acc[2][j],acc[3][j]);
}

// ---------------------------------------------------------------------------
// Phase 2: sequential scan, 2 threads per batch element.
// ---------------------------------------------------------------------------
__device__ __forceinline__ float sigm_fast(float v){
    return __fdividef(1.0f, 1.0f + __expf(-v));
}
__device__ __forceinline__ float tanh_fast(float v){
    return 1.0f - __fdividef(2.0f, __expf(2.0f*v) + 1.0f);
}

__global__ void __launch_bounds__(32) recur_kernel(
    const float* __restrict__ Wf, const float* __restrict__ Wi,
    const float* __restrict__ Wu, const float* __restrict__ Wo,
    const float* __restrict__ qwf, const float* __restrict__ qwi,
    const float* __restrict__ qwo,
    float* __restrict__ out, int write_tail)
{
    const int tid   = blockIdx.x*32 + threadIdx.x;
    const int b     = tid >> 1;
    const int lbase = (threadIdx.x & 1) * 4;   // my hidden lanes: lbase..lbase+3

    float whf[4], whi[4], who[4];
#pragma unroll
    for (int r = 0; r < 4; r++){
        whf[r] = Wf[DD + lbase + r];
        whi[r] = Wi[DD + lbase + r];
        who[r] = Wo[DD + lbase + r];
    }
    float whu[8][4];                            // [output lane j][my hx lane r]
#pragma unroll
    for (int j = 0; j < 8; j++)
#pragma unroll
        for (int r = 0; r < 4; r++)
            whu[j][r] = Wu[j*136 + DD + lbase + r];

    const float ccf = cosf(qwf[0]), cci = cosf(qwi[0]), cco = cosf(qwo[0]);

    float hx[4] = {0,0,0,0}, cx[4] = {0,0,0,0};

    const float* __restrict__ pre = g_pre + b;
    float pA[7], pB[7];

    auto LOAD = [&](float* p, int t){
        const float* q = pre + (long long)t*PSTR;
        p[0] = __ldg(q); p[1] = __ldg(q+BB); p[2] = __ldg(q+2*BB);
#pragma unroll
        for (int r = 0; r < 4; r++) p[3+r] = __ldg(q + (3 + lbase + r)*BB);
    };
    LOAD(pA, 0); LOAD(pB, 1);

    const unsigned m = 0xffffffffu;

    auto STEP = [&](int t, const float* p){
        float pf = 0.f, pi = 0.f, po = 0.f;
#pragma unroll
        for (int r = 0; r < 4; r++){
            pf = fmaf(whf[r], hx[r], pf);
            pi = fmaf(whi[r], hx[r], pi);
            po = fmaf(who[r], hx[r], po);
        }
        float pgo[4], pgx[4];
#pragma unroll
        for (int jj = 0; jj < 4; jj++){
            float so = 0.f, sx = 0.f;
#pragma unroll
            for (int r = 0; r < 4; r++){
                so = fmaf(whu[lbase + jj][r],       hx[r], so);  // my out lane
                sx = fmaf(whu[(4 - lbase) + jj][r], hx[r], sx);  // partner's
            }
            pgo[jj] = so; pgx[jj] = sx;
        }
        const float zf = pf + __shfl_xor_sync(m, pf, 1) + p[0];
        const float zi = pi + __shfl_xor_sync(m, pi, 1) + p[1];
        const float zo = po + __shfl_xor_sync(m, po, 1) + p[2];
        const float f = sigm_fast(ccf * __cosf(zf));
        const float i = sigm_fast(cci * __cosf(zi));
        const float o = sigm_fast(cco * __cosf(zo));
#pragma unroll
        for (int jj = 0; jj < 4; jj++){
            const float zg = pgo[jj] + __shfl_xor_sync(m, pgx[jj], 1) + p[3+jj];
            const float g  = tanh_fast(zg);
            cx[jj] = fmaf(f, cx[jj], i * g);
            hx[jj] = o * tanh_fast(cx[jj]);
        }
        *(float4*)(out + ((long long)t*BB + b)*8 + lbase)
            = make_float4(hx[0], hx[1], hx[2], hx[3]);
    };

    for (int t = 0; t < TT; t += 2){
        STEP(t, pA);
        int tn = t + 2; if (tn >= TT) tn = TT - 1;
        LOAD(pA, tn);
        STEP(t + 1, pB);
        int tn2 = t + 3; if (tn2 >= TT) tn2 = TT - 1;
        LOAD(pB, tn2);
    }

    if (write_tail){
        float* hp = out + (long long)TT*BB*8;
        *(float4*)(hp + b*8 + lbase)        = make_float4(hx[0],hx[1],hx[2],hx[3]);
        *(float4*)(hp + BB*8 + b*8 + lbase) = make_float4(cx[0],cx[1],cx[2],cx[3]);
    }
}

// ---------------------------------------------------------------------------
extern "C" void kernel_launch(void* const* d_in, const int* in_sizes, int n_in,
                              void* d_out, int out_size)
{
    const float* x   = (const float*)d_in[0];
    const float* Wf  = (const float*)d_in[1];
    const float* bf  = (const float*)d_in[2];
    const float* Wi  = (const float*)d_in[3];
    const float* bi  = (const float*)d_in[4];
    const float* Wu  = (const float*)d_in[5];
    const float* bu  = (const float*)d_in[6];
    const float* Wo  = (const float*)d_in[7];
    const float* bo  = (const float*)d_in[8];
    const float* qwf = (const float*)d_in[9];
    const float* qwi = (const float*)d_in[10];
    // d_in[11] = qwu: unused — the g path has no quantum gate in the reference
    const float* qwo = (const float*)d_in[12];
    float* out = (float*)d_out;

    const int write_tail = (out_size >= TT*BB*8 + 2*BB*8) ? 1 : 0;

    prep_kernel<<<1024, 128>>>(x, Wf, bf, Wi, bi, Wu, bu, Wo, bo);
    recur_kernel<<<32, 32>>>(Wf, Wi, Wu, Wo, qwf, qwi, qwo, out, write_tail);
}

// round 3
// speedup vs baseline: 1.0853x; 1.0853x over previous
#include <cuda_runtime.h>

#define TT 1024
#define BB 512
#define DD 128
#define NO 11              // k-index: 0=f,1=i,2=o,3..10=g0..g7
#define PSTR (NO*BB)

__device__ float g_pre[TT * NO * BB];   // ~23 MB scratch, [t][k][B]

// ---------------------------------------------------------------------------
// Phase 1: pre[t,k,b] = dot(Wrow_k[0:128], x[t,b,:]) + bias_k   (unchanged)
// ---------------------------------------------------------------------------
__device__ __forceinline__ float f4c(const float4 v, int kk){
    return kk==0 ? v.x : kk==1 ? v.y : kk==2 ? v.z : v.w;
}

__global__ void __launch_bounds__(128) prep_kernel(
    const float* __restrict__ x,
    const float* __restrict__ Wf, const float* __restrict__ bf,
    const float* __restrict__ Wi, const float* __restrict__ bi,
    const float* __restrict__ Wu, const float* __restrict__ bu,
    const float* __restrict__ Wo, const float* __restrict__ bo)
{
    __shared__ __align__(16) float wsm[DD*12];
    __shared__ float bsm[12];
    const int tid = threadIdx.x;
    {
        const int k = tid;
        wsm[k*12+0] = Wf[k];
        wsm[k*12+1] = Wi[k];
        wsm[k*12+2] = Wo[k];
#pragma unroll
        for (int u = 0; u < 8; u++) wsm[k*12+3+u] = Wu[u*136 + k];
        wsm[k*12+11] = 0.0f;
        if (tid == 0){
            bsm[0] = bf[0]; bsm[1] = bi[0]; bsm[2] = bo[0];
            for (int u = 0; u < 8; u++) bsm[3+u] = bu[u];
            bsm[11] = 0.0f;
        }
    }
    __syncthreads();

    const long long n0 = ((long long)blockIdx.x*128 + tid) * 4;
    const float4* __restrict__ xp = (const float4*)x + n0*(DD/4);

    float acc[4][NO];
#pragma unroll
    for (int r = 0; r < 4; r++)
#pragma unroll
        for (int j = 0; j < NO; j++) acc[r][j] = bsm[j];

#pragma unroll 2
    for (int c = 0; c < 32; c++){
        float4 xv[4];
#pragma unroll
        for (int r = 0; r < 4; r++) xv[r] = xp[r*32 + c];
#pragma unroll
        for (int kk = 0; kk < 4; kk++){
            const int k = c*4 + kk;
            const float4* wr = (const float4*)&wsm[k*12];
            const float4 wa = wr[0], wb = wr[1], wc = wr[2];
            const float w[NO] = {wa.x,wa.y,wa.z,wa.w, wb.x,wb.y,wb.z,wb.w,
                                 wc.x,wc.y,wc.z};
#pragma unroll
            for (int r = 0; r < 4; r++){
                const float xs = f4c(xv[r], kk);
#pragma unroll
                for (int j = 0; j < NO; j++)
                    acc[r][j] = fmaf(xs, w[j], acc[r][j]);
            }
        }
    }

    const int t = (int)(n0 >> 9);
    const int b = (int)(n0 & 511);
    float* op = g_pre + (long long)t*PSTR + b;
#pragma unroll
    for (int j = 0; j < NO; j++)
        *(float4*)(op + j*BB) = make_float4(acc[0][j],acc[1][j],acc[2][j],acc[3][j]);
}

// ---------------------------------------------------------------------------
// Phase 2: sequential scan, 4 threads (one quad) per batch element.
// Lane q of a quad owns hidden lanes {2q, 2q+1} and computes gate q (q<3).
// ---------------------------------------------------------------------------
__device__ __forceinline__ float tanh_fast(float v){
    return 1.0f - __fdividef(2.0f, __expf(2.0f*v) + 1.0f);
}

// sigmoid(u) for u in [-1,1]: 0.5 + u*P(u^2), |err| ~ 2e-7
__device__ __forceinline__ float sigm_poly(float u){
    const float t2 = u*u;
    float P = fmaf(t2, -2.16387e-6f,  2.13570e-5f);
    P = fmaf(t2, P, -2.10821e-4f);
    P = fmaf(t2, P,  2.0833334e-3f);
    P = fmaf(t2, P, -2.0833334e-2f);
    P = fmaf(t2, P,  0.25f);
    return fmaf(u, P, 0.5f);
}

__global__ void __launch_bounds__(32) recur_kernel(
    const float* __restrict__ Wf, const float* __restrict__ Wi,
    const float* __restrict__ Wu, const float* __restrict__ Wo,
    const float* __restrict__ qwf, const float* __restrict__ qwi,
    const float* __restrict__ qwo,
    float* __restrict__ out, int write_tail)
{
    const int lane = threadIdx.x;
    const int q    = lane & 3;                 // quad lane
    const int b    = blockIdx.x*8 + (lane >> 2);

    // Register order after allgather: [2q,2q+1, 2(q^1),2(q^1)+1,
    //                                  2(q^2),2(q^2)+1, 2(q^3),2(q^3)+1]
    int idx[8];
#pragma unroll
    for (int r = 0; r < 4; r++){ idx[2*r] = 2*(q^r); idx[2*r+1] = 2*(q^r)+1; }

    const float* gw = (q==0) ? Wf : ((q==1) ? Wi : Wo);
    float wg[8], wu0[8], wu1[8];
#pragma unroll
    for (int r = 0; r < 8; r++){
        wg[r]  = gw[DD + idx[r]];
        wu0[r] = Wu[(2*q  )*136 + DD + idx[r]];
        wu1[r] = Wu[(2*q+1)*136 + DD + idx[r]];
    }
    const float cg = cosf( (q==0) ? qwf[0] : ((q==1) ? qwi[0] : qwo[0]) );

    const int kg = (q < 3) ? q : 2;            // gate row in scratch (lane3 dummy)
    const float* __restrict__ pre = g_pre + b;

    float h0 = 0.f, h1 = 0.f, c0 = 0.f, c1 = 0.f;
    float pA[3], pB[3];

    auto LOAD = [&](float* p, int t){
        const float* base = pre + (long long)t*PSTR;
        p[0] = __ldg(base + kg*BB);
        p[1] = __ldg(base + (3 + 2*q)*BB);
        p[2] = __ldg(base + (4 + 2*q)*BB);
    };
    LOAD(pA, 0); LOAD(pB, 1);

    const unsigned m = 0xffffffffu;

    auto STEP = [&](int t, const float* p){
        // allgather hx (tree depth 2, 6 shfls)
        const float v0 = h0, v1 = h1;
        const float w0 = __shfl_xor_sync(m, v0, 1);
        const float w1 = __shfl_xor_sync(m, v1, 1);
        const float x0 = __shfl_xor_sync(m, v0, 2);
        const float x1 = __shfl_xor_sync(m, v1, 2);
        const float y0 = __shfl_xor_sync(m, w0, 2);
        const float y1 = __shfl_xor_sync(m, w1, 2);
        const float H[8] = {v0, v1, w0, w1, x0, x1, y0, y1};

        // 3 full dots, two accumulators each for ILP
        float zg = p[0], z0 = p[1], z1 = p[2];
        float zgA = 0.f, z0A = 0.f, z1A = 0.f;
#pragma unroll
        for (int r = 0; r < 8; r += 2){
            zg  = fmaf(wg [r],   H[r],   zg );
            zgA = fmaf(wg [r+1], H[r+1], zgA);
            z0  = fmaf(wu0[r],   H[r],   z0 );
            z0A = fmaf(wu0[r+1], H[r+1], z0A);
            z1  = fmaf(wu1[r],   H[r],   z1 );
            z1A = fmaf(wu1[r+1], H[r+1], z1A);
        }
        zg += zgA; z0 += z0A; z1 += z1A;

        // my gate (lane q<3: f/i/o; lane3 result unused)
        const float gate = sigm_poly(cg * __cosf(zg));

        // g-lanes (independent of gate; overlaps the broadcast)
        const float g0 = tanh_fast(z0);
        const float g1 = tanh_fast(z1);

        const float f = __shfl_sync(m, gate, 0, 4);
        const float i = __shfl_sync(m, gate, 1, 4);
        const float o = __shfl_sync(m, gate, 2, 4);

        c0 = fmaf(f, c0, i*g0);
        c1 = fmaf(f, c1, i*g1);
        h0 = o * tanh_fast(c0);
        h1 = o * tanh_fast(c1);

        *(float2*)(out + ((long long)t*BB + b)*8 + 2*q) = make_float2(h0, h1);
    };

    for (int t = 0; t < TT; t += 2){
        STEP(t, pA);
        int tn = t + 2; if (tn >= TT) tn = TT - 1;
        LOAD(pA, tn);
        STEP(t + 1, pB);
        int tn2 = t + 3; if (tn2 >= TT) tn2 = TT - 1;
        LOAD(pB, tn2);
    }

    if (write_tail){
        float* hp = out + (long long)TT*BB*8;
        *(float2*)(hp + b*8 + 2*q)         = make_float2(h0, h1);
        *(float2*)(hp + BB*8 + b*8 + 2*q)  = make_float2(c0, c1);
    }
}

// ---------------------------------------------------------------------------
extern "C" void kernel_launch(void* const* d_in, const int* in_sizes, int n_in,
                              void* d_out, int out_size)
{
    const float* x   = (const float*)d_in[0];
    const float* Wf  = (const float*)d_in[1];
    const float* bf  = (const float*)d_in[2];
    const float* Wi  = (const float*)d_in[3];
    const float* bi  = (const float*)d_in[4];
    const float* Wu  = (const float*)d_in[5];
    const float* bu  = (const float*)d_in[6];
    const float* Wo  = (const float*)d_in[7];
    const float* bo  = (const float*)d_in[8];
    const float* qwf = (const float*)d_in[9];
    const float* qwi = (const float*)d_in[10];
    // d_in[11] = qwu: unused — the g path has no quantum gate in the reference
    const float* qwo = (const float*)d_in[12];
    float* out = (float*)d_out;

    const int write_tail = (out_size >= TT*BB*8 + 2*BB*8) ? 1 : 0;

    prep_kernel<<<1024, 128>>>(x, Wf, bf, Wi, bi, Wu, bu, Wo, bo);
    recur_kernel<<<64, 32>>>(Wf, Wi, Wu, Wo, qwf, qwi, qwo, out, write_tail);
}

// round 4
// speedup vs baseline: 1.6916x; 1.5587x over previous
#include <cuda_runtime.h>

#define TT 1024
#define BB 512
#define DD 128
#define NO 11                 // 0=f,1=i,2=o,3..10=g0..g7
#define PSTR (NO*BB)
#define PREPB 256             // prep blocks; each does REPS timesteps strided by PREPB
#define REPS 4
#define RECB 16               // recur blocks (128 thr = 4 warps = 32 batch each)

__device__ float g_pre[TT * NO * BB];     // ~23 MB scratch, [t][k][B]
__device__ unsigned g_ready[TT];          // zero-initialized at load; monotonic flags

__device__ __forceinline__ float f4c(const float4 v, int kk){
    return kk==0 ? v.x : kk==1 ? v.y : kk==2 ? v.z : v.w;
}

__device__ __forceinline__ float tanh_fast(float v){
    return 1.0f - __fdividef(2.0f, __expf(2.0f*v) + 1.0f);
}

// sigmoid(u), u in [-1,1]: 0.5 + u*P(u^2), Estrin, |err| ~ 2e-7
__device__ __forceinline__ float sigm_poly(float u){
    const float t  = u*u;
    const float E0 = fmaf(t, -2.0833334e-2f, 0.25f);
    const float E1 = fmaf(t, -2.10821e-4f,   2.0833334e-3f);
    const float E2 = fmaf(t, -2.16387e-6f,   2.13570e-5f);
    const float t2 = t*t;
    const float P  = fmaf(t2, fmaf(t2, E2, E1), E0);
    return fmaf(u, P, 0.5f);
}

__global__ void __launch_bounds__(128) fused_kernel(
    const float* __restrict__ x,
    const float* __restrict__ Wf, const float* __restrict__ bf,
    const float* __restrict__ Wi, const float* __restrict__ bi,
    const float* __restrict__ Wu, const float* __restrict__ bu,
    const float* __restrict__ Wo, const float* __restrict__ bo,
    const float* __restrict__ qwf, const float* __restrict__ qwi,
    const float* __restrict__ qwo,
    float* __restrict__ out, int write_tail)
{
    const int bid = blockIdx.x;
    const int tid = threadIdx.x;

    if (bid < PREPB){
        // ================= PREP ROLE =================
        __shared__ __align__(16) float wsm[DD*12];
        __shared__ float bsm[12];
        {
            const int k = tid;
            wsm[k*12+0] = Wf[k];
            wsm[k*12+1] = Wi[k];
            wsm[k*12+2] = Wo[k];
#pragma unroll
            for (int u = 0; u < 8; u++) wsm[k*12+3+u] = Wu[u*136 + k];
            wsm[k*12+11] = 0.0f;
            if (tid == 0){
                bsm[0] = bf[0]; bsm[1] = bi[0]; bsm[2] = bo[0];
                for (int u = 0; u < 8; u++) bsm[3+u] = bu[u];
                bsm[11] = 0.0f;
            }
        }
        __syncthreads();

        for (int rep = 0; rep < REPS; rep++){
            const int t = bid + rep*PREPB;          // low t finish first
            const float4* __restrict__ xp =
                (const float4*)x + ((long long)t*BB + tid*4)*(DD/4);

            float acc[4][NO];
#pragma unroll
            for (int r = 0; r < 4; r++)
#pragma unroll
                for (int j = 0; j < NO; j++) acc[r][j] = bsm[j];

#pragma unroll 2
            for (int c = 0; c < 32; c++){
                float4 xv[4];
#pragma unroll
                for (int r = 0; r < 4; r++) xv[r] = xp[r*32 + c];
#pragma unroll
                for (int kk = 0; kk < 4; kk++){
                    const int k = c*4 + kk;
                    const float4* wr = (const float4*)&wsm[k*12];
                    const float4 wa = wr[0], wb = wr[1], wc = wr[2];
                    const float w[NO] = {wa.x,wa.y,wa.z,wa.w,
                                         wb.x,wb.y,wb.z,wb.w,
                                         wc.x,wc.y,wc.z};
#pragma unroll
                    for (int r = 0; r < 4; r++){
                        const float xs = f4c(xv[r], kk);
#pragma unroll
                        for (int j = 0; j < NO; j++)
                            acc[r][j] = fmaf(xs, w[j], acc[r][j]);
                    }
                }
            }

            float* op = g_pre + (long long)t*PSTR + tid*4;
#pragma unroll
            for (int j = 0; j < NO; j++)
                *(float4*)(op + j*BB) =
                    make_float4(acc[0][j],acc[1][j],acc[2][j],acc[3][j]);

            __threadfence();
            __syncthreads();
            if (tid == 0)
                asm volatile("st.release.gpu.global.b32 [%0], %1;"
                             :: "l"(&g_ready[t]), "r"(1u) : "memory");
        }
        return;
    }

    // ================= RECUR ROLE =================
    const int rb   = bid - PREPB;
    const int lane = tid & 31;
    const int q    = lane & 3;                       // quad lane: gate f/i/o/-
    const int b    = rb*32 + (tid >> 5)*8 + ((lane >> 2) & 7);

    int idx[8];
#pragma unroll
    for (int r = 0; r < 4; r++){ idx[2*r] = 2*(q^r); idx[2*r+1] = 2*(q^r)+1; }

    const float* gw = (q==0) ? Wf : ((q==1) ? Wi : Wo);
    float wg[8], wu0[8], wu1[8];
#pragma unroll
    for (int r = 0; r < 8; r++){
        wg[r]  = gw[DD + idx[r]];
        wu0[r] = Wu[(2*q  )*136 + DD + idx[r]];
        wu1[r] = Wu[(2*q+1)*136 + DD + idx[r]];
    }
    const float cg = cosf( (q==0) ? qwf[0] : ((q==1) ? qwi[0] : qwo[0]) );
    const int kg = (q < 3) ? q : 2;

    const float* __restrict__ pre = g_pre + b;

    float h0 = 0.f, h1 = 0.f, c0 = 0.f, c1 = 0.f;
    float pr[8][3];

    const unsigned m = 0xffffffffu;

    auto POLL = [&](int tbase){
        int tp = tbase + (lane & 7);
        if (tp > TT-1) tp = TT-1;
        const unsigned* fp = &g_ready[tp];
        unsigned v;
        do {
            asm volatile("ld.acquire.gpu.global.b32 %0, [%1];"
                         : "=r"(v) : "l"(fp) : "memory");
        } while (!__all_sync(m, v != 0));
        asm volatile("fence.acq_rel.gpu;" ::: "memory");
    };

    auto LOAD = [&](float* p, int t){
        const float* base = pre + (long long)t*PSTR;
        p[0] = __ldg(base + kg*BB);
        p[1] = __ldg(base + (3 + 2*q)*BB);
        p[2] = __ldg(base + (4 + 2*q)*BB);
    };

    auto STEP = [&](int t, const float* p){
        // allgather hx across the quad (6 shfls, tree depth 2)
        const float v0 = h0, v1 = h1;
        const float w0 = __shfl_xor_sync(m, v0, 1);
        const float w1 = __shfl_xor_sync(m, v1, 1);
        const float x0 = __shfl_xor_sync(m, v0, 2);
        const float x1 = __shfl_xor_sync(m, v1, 2);
        const float y0 = __shfl_xor_sync(m, w0, 2);
        const float y1 = __shfl_xor_sync(m, w1, 2);
        const float H[8] = {v0, v1, w0, w1, x0, x1, y0, y1};

        float zg = p[0], z0 = p[1], z1 = p[2];
        float zgA = 0.f, z0A = 0.f, z1A = 0.f;
#pragma unroll
        for (int r = 0; r < 8; r += 2){
            zg  = fmaf(wg [r],   H[r],   zg );
            zgA = fmaf(wg [r+1], H[r+1], zgA);
            z0  = fmaf(wu0[r],   H[r],   z0 );
            z0A = fmaf(wu0[r+1], H[r+1], z0A);
            z1  = fmaf(wu1[r],   H[r],   z1 );
            z1A = fmaf(wu1[r+1], H[r+1], z1A);
        }
        zg += zgA; z0 += z0A; z1 += z1A;

        const float gate = sigm_poly(cg * __cosf(zg));
        const float g0 = tanh_fast(z0);
        const float g1 = tanh_fast(z1);

        const float f = __shfl_sync(m, gate, 0, 4);
        const float i = __shfl_sync(m, gate, 1, 4);
        const float o = __shfl_sync(m, gate, 2, 4);

        c0 = fmaf(f, c0, i*g0);
        c1 = fmaf(f, c1, i*g1);
        h0 = o * tanh_fast(c0);
        h1 = o * tanh_fast(c1);

        *(float2*)(out + ((long long)t*BB + b)*8 + 2*q) = make_float2(h0, h1);
    };

    POLL(0);
#pragma unroll
    for (int ph = 0; ph < 8; ph++) LOAD(pr[ph], ph);

    for (int tb = 0; tb < TT; tb += 8){
        POLL(tb + 8);                    // clamped inside; cheap when already set
#pragma unroll
        for (int ph = 0; ph < 8; ph++){
            STEP(tb + ph, pr[ph]);
            int tn = tb + ph + 8; if (tn >= TT) tn = TT - 1;
            LOAD(pr[ph], tn);
        }
    }

    if (write_tail){
        float* hp = out + (long long)TT*BB*8;
        *(float2*)(hp + b*8 + 2*q)        = make_float2(h0, h1);
        *(float2*)(hp + BB*8 + b*8 + 2*q) = make_float2(c0, c1);
    }
}

// ---------------------------------------------------------------------------
extern "C" void kernel_launch(void* const* d_in, const int* in_sizes, int n_in,
                              void* d_out, int out_size)
{
    const float* x   = (const float*)d_in[0];
    const float* Wf  = (const float*)d_in[1];
    const float* bf  = (const float*)d_in[2];
    const float* Wi  = (const float*)d_in[3];
    const float* bi  = (const float*)d_in[4];
    const float* Wu  = (const float*)d_in[5];
    const float* bu  = (const float*)d_in[6];
    const float* Wo  = (const float*)d_in[7];
    const float* bo  = (const float*)d_in[8];
    const float* qwf = (const float*)d_in[9];
    const float* qwi = (const float*)d_in[10];
    // d_in[11] = qwu: unused — g path has no quantum gate in the reference
    const float* qwo = (const float*)d_in[12];
    float* out = (float*)d_out;

    const int write_tail = (out_size >= TT*BB*8 + 2*BB*8) ? 1 : 0;

    fused_kernel<<<PREPB + RECB, 128>>>(x, Wf, bf, Wi, bi, Wu, bu, Wo, bo,
                                        qwf, qwi, qwo, out, write_tail);
}